// round 5
// baseline (speedup 1.0000x reference)
#include <cuda_runtime.h>

#define BB 8
#define LL 4096
#define DD 1024
#define MAXW 720
#define CH 8             // channels per MA block
#define CHUNK 512
#define RING 1024
#define RPAD 1036        // ring row stride (floats; 4*RPAD % 32 == 16 -> no aliasing)
#define XPAD 524         // x-tile row stride (floats)

// ---------------------------------------------------------------------------
// Moving-average half via prefix sums.
//   y[t] = x[t] + m1*(S[t]-S[t-w]),  S = inclusive prefix sum,  m1 = -1/w
// CHUNK=512 with RING=1024: slots needed for lookback w>512 are overwritten by
// this chunk's own scan, so phase A pre-reads those old S values into registers
// BEFORE phase B writes the ring.
// ---------------------------------------------------------------------------
__global__ __launch_bounds__(256, 4) void ma_kernel(const float* __restrict__ u,
                                                    const float* __restrict__ ma_k,
                                                    float* __restrict__ out) {
    extern __shared__ float sm[];
    float* ring  = sm;                      // CH * RPAD  (S ring, 1024 deep)
    float* xtile = sm + CH * RPAD;          // CH * XPAD  (x chunk, transposed)
    float* m1s   = xtile + CH * XPAD;       // CH
    int*   wss   = (int*)(m1s + CH);        // CH

    const int tid  = threadIdx.x;
    const int warp = tid >> 5;
    const int lane = tid & 31;
    const int grp  = blockIdx.x;                  // 0..63
    const int g32  = 2 * (grp >> 2) + 1;          // odd 32-channel group
    const int d0   = g32 * 32 + (grp & 3) * 8;
    const int b    = blockIdx.y;

    const float4* u4 = (const float4*)u;
    float4*       o4 = (float4*)out;
    const size_t base4 = (size_t)b * LL * (DD / 4) + (d0 >> 2);

    if (tid < CH) {
        const int d = d0 + tid;
        const int i_ma = ((d >> 6) << 2) + ((d >> 3) & 7) - 4;   // 0..63
        const float m1 = ma_k[i_ma * MAXW + 1];                  // = -1/w
        m1s[tid] = m1;
        wss[tid] = (int)rintf(-1.0f / m1);
    }
    __syncthreads();

    const int c4 = tid & 1;          // float4 column (8 ch = 2 float4)
    const int r0 = tid >> 1;         // row 0..127

    // per-thread params for its 4 channels
    float m1r[4]; int wr[4];
    #pragma unroll
    for (int j = 0; j < 4; j++) { m1r[j] = m1s[c4 * 4 + j]; wr[j] = wss[c4 * 4 + j]; }

    float carry = 0.0f;              // scan carry (channel = warp)

    for (int t0 = 0; t0 < LL; t0 += CHUNK) {
        // ---- Phase A: load x tile + pre-read endangered old S values ----
        float pre[4][4];
        #pragma unroll
        for (int k = 0; k < 4; k++) {
            const int r = r0 + 128 * k;
            const int t = t0 + r;
            const float4 f = u4[base4 + (size_t)t * (DD / 4) + c4];
            float* col = xtile + (c4 * 4) * XPAD + r;
            col[0 * XPAD] = f.x; col[1 * XPAD] = f.y;
            col[2 * XPAD] = f.z; col[3 * XPAD] = f.w;
            #pragma unroll
            for (int j = 0; j < 4; j++) {
                const int tw = t - wr[j];
                // valid old slot: tw in [t0-1024, t0); tw<0 (t<w) must yield 0
                pre[k][j] = (tw >= 0 && tw < t0)
                          ? ring[(c4 * 4 + j) * RPAD + (tw & (RING - 1))] : 0.0f;
            }
        }
        __syncthreads();

        // ---- Phase B: warp w scans channel w (2 sub-scans of 256) ----
        {
            const float* trow = xtile + warp * XPAD;
            float* rrow = ring + warp * RPAD;
            #pragma unroll
            for (int s = 0; s < CHUNK / 256; s++) {
                const float4 a  = *(const float4*)(trow + s * 256 + lane * 8);
                const float4 bq = *(const float4*)(trow + s * 256 + lane * 8 + 4);
                float p0 = a.x,       p1 = p0 + a.y,  p2 = p1 + a.z,  p3 = p2 + a.w;
                float p4 = p3 + bq.x, p5 = p4 + bq.y, p6 = p5 + bq.z, p7 = p6 + bq.w;
                float v = p7;
                #pragma unroll
                for (int off = 1; off < 32; off <<= 1) {
                    const float n = __shfl_up_sync(0xffffffffu, v, off);
                    if (lane >= off) v += n;
                }
                const float bs = (v - p7) + carry;      // exclusive prefix + carry
                float4 s0, s1;
                s0.x = p0 + bs; s0.y = p1 + bs; s0.z = p2 + bs; s0.w = p3 + bs;
                s1.x = p4 + bs; s1.y = p5 + bs; s1.z = p6 + bs; s1.w = p7 + bs;
                const int rb = (t0 + s * 256) & (RING - 1);
                *(float4*)(rrow + rb + lane * 8)     = s0;
                *(float4*)(rrow + rb + lane * 8 + 4) = s1;
                carry += __shfl_sync(0xffffffffu, v, 31);
            }
        }
        __syncthreads();

        // ---- Phase C: y = x + m1*(S - S_old), coalesced float4 store ----
        #pragma unroll
        for (int k = 0; k < 4; k++) {
            const int r = r0 + 128 * k;
            const int t = t0 + r;
            float4 y;
            float* yp = (float*)&y;
            #pragma unroll
            for (int j = 0; j < 4; j++) {
                const int ch = c4 * 4 + j;
                const int tw = t - wr[j];
                const float x  = xtile[ch * XPAD + r];
                const float S  = ring[ch * RPAD + (t & (RING - 1))];
                // tw >= t0: written by this chunk's phase B (fresh, safe)
                // tw <  t0: register pre-read (includes 0 for tw < 0)
                const float So = (tw >= t0) ? ring[ch * RPAD + (tw & (RING - 1))]
                                            : pre[k][j];
                yp[j] = fmaf(m1r[j], S - So, x);
            }
            o4[base4 + (size_t)t * (DD / 4) + c4] = y;
        }
        __syncthreads();
    }
}

// ---------------------------------------------------------------------------
// Differencing half: even 32-channel groups, 4-tap causal stencil (R2 best).
// ---------------------------------------------------------------------------
__global__ __launch_bounds__(256) void diff_stencil_kernel(const float* __restrict__ u,
                                                           const float* __restrict__ dk,
                                                           float* __restrict__ out) {
    const int g  = blockIdx.x;                        // 0..15
    const int d  = g * 64 + threadIdx.x;              // 32 channels, even 32-group
    const int b  = blockIdx.z;
    const int t0 = (blockIdx.y * 8 + threadIdx.y) * 16;

    const int nk = (d >> 3) & 3;
    const float c0 = dk[nk * 4 + 0];
    const float c1 = dk[nk * 4 + 1];
    const float c2 = dk[nk * 4 + 2];
    const float c3 = dk[nk * 4 + 3];

    const size_t base = (size_t)b * LL * DD + d;

    float x1 = (t0 >= 1) ? u[base + (size_t)(t0 - 1) * DD] : 0.0f;
    float x2 = (t0 >= 2) ? u[base + (size_t)(t0 - 2) * DD] : 0.0f;
    float x3 = (t0 >= 3) ? u[base + (size_t)(t0 - 3) * DD] : 0.0f;

    #pragma unroll
    for (int tt = 0; tt < 16; tt++) {
        const int t = t0 + tt;
        const float x0 = u[base + (size_t)t * DD];
        out[base + (size_t)t * DD] = c0 * x0 + c1 * x1 + c2 * x2 + c3 * x3;
        x3 = x2; x2 = x1; x1 = x0;
    }
}

extern "C" void kernel_launch(void* const* d_in, const int* in_sizes, int n_in,
                              void* d_out, int out_size) {
    const float* u  = (const float*)d_in[0];   // (B, L, D)
    const float* dk = (const float*)d_in[1];   // (64, 4)
    const float* mk = (const float*)d_in[2];   // (64, 720)
    float* out = (float*)d_out;                // (B, L, D)

    const size_t smem = (size_t)(CH * RPAD + CH * XPAD + CH) * sizeof(float)
                      + (size_t)CH * sizeof(int);
    cudaFuncSetAttribute(ma_kernel, cudaFuncAttributeMaxDynamicSharedMemorySize, (int)smem);

    // diff first, MA second: ncu (-s 5 -c 1) captures the 2nd launch -> profiles MA
    diff_stencil_kernel<<<dim3(16, 32, BB), dim3(32, 8)>>>(u, dk, out);
    ma_kernel<<<dim3(64, BB), 256, smem>>>(u, mk, out);
}

// round 6
// speedup vs baseline: 1.1456x; 1.1456x over previous
#include <cuda_runtime.h>

#define BB 8
#define LL 4096
#define DD 1024
#define MAXW 720
#define CH 8               // channels per MA block
#define TILE 2048          // output timesteps per block
#define HALO 768           // >= MAXW-1, multiple of 256
#define SPAN (TILE + HALO) // 2816 = 11 * 256
#define PAD 2820           // row stride (floats): 4*PAD % 32 == 16 -> conflict-free

// ---------------------------------------------------------------------------
// Moving-average half via LOCAL prefix sums (no cross-tile carry).
//   y[t] = (S[t]-S[t-1]) + m1*(S[t]-S[t-w]),  m1 = -1/w
// Each block: 8 channels x (TILE + HALO) timesteps. Halo makes tiles
// independent; zero-filled halo of tile 0 handles all t<w edge cases with no
// predicates. Three phases, two barriers per block.
// ---------------------------------------------------------------------------
__global__ __launch_bounds__(256, 2) void ma_kernel(const float* __restrict__ u,
                                                    const float* __restrict__ ma_k,
                                                    float* __restrict__ out) {
    extern __shared__ float sm[];
    float* tile = sm;                       // CH * PAD floats (x, then S in place)

    const int tid  = threadIdx.x;
    const int warp = tid >> 5;
    const int lane = tid & 31;
    const int grp  = blockIdx.x;                  // 0..63 : 8-channel group
    const int lt   = blockIdx.y;                  // L-tile index (0..1)
    const int b    = blockIdx.z;
    const int g32  = 2 * (grp >> 2) + 1;          // odd 32-channel group
    const int d0   = g32 * 32 + (grp & 3) * 8;
    const int T0   = lt * TILE;

    const float4* u4 = (const float4*)u;
    float4*       o4 = (float4*)out;
    const size_t base4 = (size_t)b * LL * (DD / 4) + (d0 >> 2);

    const int c4 = tid & 1;          // float4 column (8 ch = 2 float4)
    const int r0 = tid >> 1;         // row 0..127

    // per-thread params for its 4 output channels
    float m1r[4]; int wr[4];
    #pragma unroll
    for (int j = 0; j < 4; j++) {
        const int d = d0 + c4 * 4 + j;
        const int i_ma = ((d >> 6) << 2) + ((d >> 3) & 7) - 4;   // 0..63
        m1r[j] = __ldg(&ma_k[i_ma * MAXW + 1]);                  // = -1/w
        wr[j]  = (int)rintf(-1.0f / m1r[j]);
    }

    // ---- Phase A: load x (tile + halo), transposed; zero-fill t<0 ----
    #pragma unroll 4
    for (int k = 0; k < SPAN / 128; k++) {
        const int r = r0 + 128 * k;              // local row 0..SPAN-1
        const int t = T0 - HALO + r;             // global time
        float4 f = {0.f, 0.f, 0.f, 0.f};
        if (t >= 0) f = u4[base4 + (size_t)t * (DD / 4) + c4];
        float* col = tile + (c4 * 4) * PAD + r;
        col[0 * PAD] = f.x; col[1 * PAD] = f.y;
        col[2 * PAD] = f.z; col[3 * PAD] = f.w;
    }
    __syncthreads();

    // ---- Phase B: warp w scans channel w in place (11 sub-scans of 256) ----
    {
        float* trow = tile + warp * PAD;
        float carry = 0.0f;
        #pragma unroll
        for (int s = 0; s < SPAN / 256; s++) {
            float4 a  = *(const float4*)(trow + s * 256 + lane * 8);
            float4 bq = *(const float4*)(trow + s * 256 + lane * 8 + 4);
            float p0 = a.x,       p1 = p0 + a.y,  p2 = p1 + a.z,  p3 = p2 + a.w;
            float p4 = p3 + bq.x, p5 = p4 + bq.y, p6 = p5 + bq.z, p7 = p6 + bq.w;
            float v = p7;
            #pragma unroll
            for (int off = 1; off < 32; off <<= 1) {
                const float n = __shfl_up_sync(0xffffffffu, v, off);
                if (lane >= off) v += n;
            }
            const float bs = (v - p7) + carry;        // exclusive prefix + carry
            a.x = p0 + bs; a.y = p1 + bs; a.z = p2 + bs; a.w = p3 + bs;
            bq.x = p4 + bs; bq.y = p5 + bs; bq.z = p6 + bs; bq.w = p7 + bs;
            *(float4*)(trow + s * 256 + lane * 8)     = a;
            *(float4*)(trow + s * 256 + lane * 8 + 4) = bq;
            carry += __shfl_sync(0xffffffffu, v, 31);
        }
    }
    __syncthreads();

    // ---- Phase C: y = (S-S[-1]) + m1*(S-S[-w]), coalesced float4 store ----
    #pragma unroll 4
    for (int k = 0; k < TILE / 128; k++) {
        const int r  = r0 + 128 * k;
        const int hr = r + HALO;                 // local index of output element
        float4 y;
        float* yp = (float*)&y;
        #pragma unroll
        for (int j = 0; j < 4; j++) {
            const float* trow = tile + (c4 * 4 + j) * PAD;
            const float S  = trow[hr];
            const float Sm = trow[hr - 1];
            const float So = trow[hr - wr[j]];
            yp[j] = fmaf(m1r[j], S - So, S - Sm);
        }
        o4[base4 + (size_t)(T0 + r) * (DD / 4) + c4] = y;
    }
}

// ---------------------------------------------------------------------------
// Differencing half: even 32-channel groups, 4-tap causal stencil (R2 best).
// ---------------------------------------------------------------------------
__global__ __launch_bounds__(256) void diff_stencil_kernel(const float* __restrict__ u,
                                                           const float* __restrict__ dk,
                                                           float* __restrict__ out) {
    const int g  = blockIdx.x;                        // 0..15
    const int d  = g * 64 + threadIdx.x;              // 32 channels, even 32-group
    const int b  = blockIdx.z;
    const int t0 = (blockIdx.y * 8 + threadIdx.y) * 16;

    const int nk = (d >> 3) & 3;
    const float c0 = dk[nk * 4 + 0];
    const float c1 = dk[nk * 4 + 1];
    const float c2 = dk[nk * 4 + 2];
    const float c3 = dk[nk * 4 + 3];

    const size_t base = (size_t)b * LL * DD + d;

    float x1 = (t0 >= 1) ? u[base + (size_t)(t0 - 1) * DD] : 0.0f;
    float x2 = (t0 >= 2) ? u[base + (size_t)(t0 - 2) * DD] : 0.0f;
    float x3 = (t0 >= 3) ? u[base + (size_t)(t0 - 3) * DD] : 0.0f;

    #pragma unroll
    for (int tt = 0; tt < 16; tt++) {
        const int t = t0 + tt;
        const float x0 = u[base + (size_t)t * DD];
        out[base + (size_t)t * DD] = c0 * x0 + c1 * x1 + c2 * x2 + c3 * x3;
        x3 = x2; x2 = x1; x1 = x0;
    }
}

extern "C" void kernel_launch(void* const* d_in, const int* in_sizes, int n_in,
                              void* d_out, int out_size) {
    const float* u  = (const float*)d_in[0];   // (B, L, D)
    const float* dk = (const float*)d_in[1];   // (64, 4)
    const float* mk = (const float*)d_in[2];   // (64, 720)
    float* out = (float*)d_out;                // (B, L, D)

    const size_t smem = (size_t)(CH * PAD) * sizeof(float);
    cudaFuncSetAttribute(ma_kernel, cudaFuncAttributeMaxDynamicSharedMemorySize, (int)smem);

    // diff first, MA second: ncu (-s 5 -c 1) captures the 2nd launch -> profiles MA
    diff_stencil_kernel<<<dim3(16, 32, BB), dim3(32, 8)>>>(u, dk, out);
    ma_kernel<<<dim3(64, 2, BB), 256, smem>>>(u, mk, out);
}